// round 6
// baseline (speedup 1.0000x reference)
#include <cuda_runtime.h>
#include <cstdint>

// out[i] = 0.5 * sum_{bonds b with adj[b,0]==i} par[b] * (|xyz[adj0]-xyz[adj1]| - len[b])^2
// NOTE: bond_adj arrives as int32 (JAX x64-disabled downcasts the requested int64).

__global__ void zero_out_kernel(float* __restrict__ out, int n)
{
    int i = blockIdx.x * blockDim.x + threadIdx.x;
    if (i < n) out[i] = 0.0f;
}

__global__ void __launch_bounds__(256)
bond_energy_kernel(const float* __restrict__ xyz,
                   const int2*  __restrict__ adj,   // [E] pairs of int32
                   const float* __restrict__ blen,  // [E]
                   const float* __restrict__ bpar,  // [E]
                   float* __restrict__ out,         // [N]
                   int nbonds)
{
    int e = blockIdx.x * blockDim.x + threadIdx.x;
    if (e >= nbonds) return;

    // 8B coalesced vector load of the index pair
    int2 ij = __ldg(adj + e);
    int i = ij.x;
    int j = ij.y;

    // Gather endpoint coords (xyz is 24MB -> L2-resident after warmup)
    const float* pi = xyz + (size_t)i * 3;
    const float* pj = xyz + (size_t)j * 3;
    float dx = __ldg(pi + 0) - __ldg(pj + 0);
    float dy = __ldg(pi + 1) - __ldg(pj + 1);
    float dz = __ldg(pi + 2) - __ldg(pj + 2);

    float d  = sqrtf(fmaf(dx, dx, fmaf(dy, dy, dz * dz)));
    float t  = d - __ldg(blen + e);
    float en = 0.5f * __ldg(bpar + e) * t * t;

    atomicAdd(out + i, en);
}

extern "C" void kernel_launch(void* const* d_in, const int* in_sizes, int n_in,
                              void* d_out, int out_size)
{
    const float* xyz  = (const float*)d_in[0];  // [N,3]
    const int2*  adj  = (const int2*)d_in[1];   // [E,2] int32
    const float* blen = (const float*)d_in[2];  // [E,1]
    const float* bpar = (const float*)d_in[3];  // [E,1]
    float*       out  = (float*)d_out;          // [N,1]

    int nbonds = in_sizes[1] / 2;   // adj has E*2 elements
    int natoms = out_size;

    {
        int threads = 256;
        int blocks  = (natoms + threads - 1) / threads;
        zero_out_kernel<<<blocks, threads>>>(out, natoms);
    }
    {
        int threads = 256;
        int blocks  = (nbonds + threads - 1) / threads;
        bond_energy_kernel<<<blocks, threads>>>(xyz, adj, blen, bpar, out, nbonds);
    }
}

// round 7
// speedup vs baseline: 1.1014x; 1.1014x over previous
#include <cuda_runtime.h>
#include <cstdint>

// out[i] = 0.5 * sum_{bonds b with adj[b,0]==i} par[b] * (|xyz[a0]-xyz[a1]| - len[b])^2
// bond_adj arrives as int32 (JAX x64-disabled downcasts int64).
//
// Strategy: repack xyz [N,3] -> xyz4 [N] float4 (16B-aligned) so each endpoint
// gather is ONE LDG.128 wavefront instead of three LDG.32 wavefronts.

#define MAX_ATOMS 2000000
__device__ float4 g_xyz4[MAX_ATOMS];   // 32 MB scratch (static, allowed)

__global__ void zero_out_kernel(float* __restrict__ out, int n)
{
    int i = blockIdx.x * blockDim.x + threadIdx.x;
    if (i < n) out[i] = 0.0f;
}

__global__ void __launch_bounds__(256)
repack_xyz_kernel(const float* __restrict__ xyz, int natoms)
{
    int i = blockIdx.x * blockDim.x + threadIdx.x;
    if (i >= natoms) return;
    const float* p = xyz + (size_t)i * 3;
    float4 v;
    v.x = __ldg(p + 0);
    v.y = __ldg(p + 1);
    v.z = __ldg(p + 2);
    v.w = 0.0f;
    g_xyz4[i] = v;
}

__global__ void __launch_bounds__(256)
bond_energy_kernel(const int2*  __restrict__ adj,   // [E] pairs of int32
                   const float* __restrict__ blen,  // [E]
                   const float* __restrict__ bpar,  // [E]
                   float* __restrict__ out,         // [N]
                   int nbonds)
{
    int e = blockIdx.x * blockDim.x + threadIdx.x;
    if (e >= nbonds) return;

    int2 ij = __ldg(adj + e);

    // single 16B gather per endpoint (L2-resident 32MB table)
    float4 a = __ldg(&g_xyz4[ij.x]);
    float4 b = __ldg(&g_xyz4[ij.y]);

    float dx = a.x - b.x;
    float dy = a.y - b.y;
    float dz = a.z - b.z;

    float d  = sqrtf(fmaf(dx, dx, fmaf(dy, dy, dz * dz)));
    float t  = d - __ldg(blen + e);
    float en = 0.5f * __ldg(bpar + e) * t * t;

    atomicAdd(out + ij.x, en);
}

extern "C" void kernel_launch(void* const* d_in, const int* in_sizes, int n_in,
                              void* d_out, int out_size)
{
    const float* xyz  = (const float*)d_in[0];  // [N,3]
    const int2*  adj  = (const int2*)d_in[1];   // [E,2] int32
    const float* blen = (const float*)d_in[2];  // [E,1]
    const float* bpar = (const float*)d_in[3];  // [E,1]
    float*       out  = (float*)d_out;          // [N,1]

    int nbonds = in_sizes[1] / 2;
    int natoms = out_size;

    {
        int threads = 256;
        zero_out_kernel<<<(natoms + threads - 1) / threads, threads>>>(out, natoms);
        repack_xyz_kernel<<<(natoms + threads - 1) / threads, threads>>>(xyz, natoms);
    }
    {
        int threads = 256;
        bond_energy_kernel<<<(nbonds + threads - 1) / threads, threads>>>(adj, blen, bpar, out, nbonds);
    }
}

// round 10
// speedup vs baseline: 1.1865x; 1.0773x over previous
#include <cuda_runtime.h>
#include <cstdint>

// out[i] = 0.5 * sum_{bonds b with adj[b,0]==i} par[b] * (|xyz[a0]-xyz[a1]| - len[b])^2
// bond_adj arrives as int32 (JAX x64-disabled downcasts int64).
//
// L2-sector-roofline design:
//  - xyz repacked to float4 (1 LDG.128 = 1 sector per endpoint gather)
//  - zero_out fused into repack (one prep launch)
//  - 4 bonds/thread, vectorized streams (int4 x2, float4 len, float4 par) for MLP

#define MAX_ATOMS 2000000
__device__ float4 g_xyz4[MAX_ATOMS];   // 32 MB static scratch

// Fused: zero output + repack xyz [N,3] -> float4 table
__global__ void __launch_bounds__(256)
prep_kernel(const float* __restrict__ xyz, float* __restrict__ out, int natoms)
{
    int i = blockIdx.x * blockDim.x + threadIdx.x;
    if (i >= natoms) return;
    out[i] = 0.0f;
    const float* p = xyz + (size_t)i * 3;
    float4 v;
    v.x = __ldg(p + 0);
    v.y = __ldg(p + 1);
    v.z = __ldg(p + 2);
    v.w = 0.0f;
    g_xyz4[i] = v;
}

__device__ __forceinline__ float bond_e(float4 a, float4 b, float len, float par)
{
    float dx = a.x - b.x;
    float dy = a.y - b.y;
    float dz = a.z - b.z;
    float d  = sqrtf(fmaf(dx, dx, fmaf(dy, dy, dz * dz)));
    float t  = d - len;
    return 0.5f * par * t * t;
}

// 4 bonds per thread
__global__ void __launch_bounds__(256)
bond_energy_kernel(const int4*   __restrict__ adj2,  // [E/2] two pairs per int4
                   const float4* __restrict__ blen4, // [E/4]
                   const float4* __restrict__ bpar4, // [E/4]
                   float* __restrict__ out,          // [N]
                   int nquads)                       // E/4
{
    int q = blockIdx.x * blockDim.x + threadIdx.x;
    if (q >= nquads) return;

    // two int4 loads = 4 index pairs
    int4 p01 = __ldg(adj2 + 2 * q);
    int4 p23 = __ldg(adj2 + 2 * q + 1);
    float4 len = __ldg(blen4 + q);
    float4 par = __ldg(bpar4 + q);

    // issue all 8 gathers up front (MLP)
    float4 a0 = __ldg(&g_xyz4[p01.x]);
    float4 b0 = __ldg(&g_xyz4[p01.y]);
    float4 a1 = __ldg(&g_xyz4[p01.z]);
    float4 b1 = __ldg(&g_xyz4[p01.w]);
    float4 a2 = __ldg(&g_xyz4[p23.x]);
    float4 b2 = __ldg(&g_xyz4[p23.y]);
    float4 a3 = __ldg(&g_xyz4[p23.z]);
    float4 b3 = __ldg(&g_xyz4[p23.w]);

    atomicAdd(out + p01.x, bond_e(a0, b0, len.x, par.x));
    atomicAdd(out + p01.z, bond_e(a1, b1, len.y, par.y));
    atomicAdd(out + p23.x, bond_e(a2, b2, len.z, par.z));
    atomicAdd(out + p23.z, bond_e(a3, b3, len.w, par.w));
}

// Tail kernel for nbonds not divisible by 4 (generic scalar path)
__global__ void __launch_bounds__(128)
bond_energy_tail_kernel(const int2*  __restrict__ adj,
                        const float* __restrict__ blen,
                        const float* __restrict__ bpar,
                        float* __restrict__ out,
                        int start, int nbonds)
{
    int e = start + blockIdx.x * blockDim.x + threadIdx.x;
    if (e >= nbonds) return;
    int2 ij = __ldg(adj + e);
    float4 a = __ldg(&g_xyz4[ij.x]);
    float4 b = __ldg(&g_xyz4[ij.y]);
    atomicAdd(out + ij.x, bond_e(a, b, __ldg(blen + e), __ldg(bpar + e)));
}

extern "C" void kernel_launch(void* const* d_in, const int* in_sizes, int n_in,
                              void* d_out, int out_size)
{
    const float* xyz  = (const float*)d_in[0];  // [N,3]
    const int2*  adj  = (const int2*)d_in[1];   // [E,2] int32
    const float* blen = (const float*)d_in[2];  // [E,1]
    const float* bpar = (const float*)d_in[3];  // [E,1]
    float*       out  = (float*)d_out;          // [N,1]

    int nbonds = in_sizes[1] / 2;
    int natoms = out_size;
    int nquads = nbonds / 4;
    int tail   = nquads * 4;

    {
        int threads = 256;
        prep_kernel<<<(natoms + threads - 1) / threads, threads>>>(xyz, out, natoms);
    }
    if (nquads > 0) {
        int threads = 256;
        bond_energy_kernel<<<(nquads + threads - 1) / threads, threads>>>(
            (const int4*)adj, (const float4*)blen, (const float4*)bpar, out, nquads);
    }
    if (tail < nbonds) {
        int threads = 128;
        int n = nbonds - tail;
        bond_energy_tail_kernel<<<(n + threads - 1) / threads, threads>>>(
            adj, blen, bpar, out, tail, nbonds);
    }
}

// round 11
// speedup vs baseline: 1.2183x; 1.0268x over previous
#include <cuda_runtime.h>
#include <cstdint>

// out[i] = 0.5 * sum_{bonds b with adj[b,0]==i} par[b] * (|xyz[a0]-xyz[a1]| - len[b])^2
// bond_adj arrives as int32 (JAX x64-disabled downcasts int64).
//
// Gather-wavefront-roofline design:
//  - xyz repacked to float4 (1 LDG.128 = 1 sector = 1 wavefront per endpoint gather)
//  - zero_out fused into repack (one prep launch)
//  - 2 bonds/thread (int4 adj = 2 pairs, float2 len/par), low regs -> high occupancy
//    so enough gathers are in flight to saturate the L1tex/LTS pipes.

#define MAX_ATOMS 2000000
__device__ float4 g_xyz4[MAX_ATOMS];   // 32 MB static scratch

// Fused: zero output + repack xyz [N,3] -> float4 table
__global__ void __launch_bounds__(256)
prep_kernel(const float* __restrict__ xyz, float* __restrict__ out, int natoms)
{
    int i = blockIdx.x * blockDim.x + threadIdx.x;
    if (i >= natoms) return;
    out[i] = 0.0f;
    const float* p = xyz + (size_t)i * 3;
    float4 v;
    v.x = __ldg(p + 0);
    v.y = __ldg(p + 1);
    v.z = __ldg(p + 2);
    v.w = 0.0f;
    g_xyz4[i] = v;
}

__device__ __forceinline__ float bond_e(float4 a, float4 b, float len, float par)
{
    float dx = a.x - b.x;
    float dy = a.y - b.y;
    float dz = a.z - b.z;
    float d  = sqrtf(fmaf(dx, dx, fmaf(dy, dy, dz * dz)));
    float t  = d - len;
    return 0.5f * par * t * t;
}

// 2 bonds per thread, 6 CTAs/SM target
__global__ void __launch_bounds__(256, 6)
bond_energy_kernel(const int4*   __restrict__ adj2,  // [E/2]: two pairs per int4
                   const float2* __restrict__ blen2, // [E/2]
                   const float2* __restrict__ bpar2, // [E/2]
                   float* __restrict__ out,          // [N]
                   int npairs)                       // E/2
{
    int p = blockIdx.x * blockDim.x + threadIdx.x;
    if (p >= npairs) return;

    int4   ij  = __ldg(adj2 + p);    // (i0,j0,i1,j1)
    float2 len = __ldg(blen2 + p);
    float2 par = __ldg(bpar2 + p);

    // 4 independent gathers in flight
    float4 a0 = __ldg(&g_xyz4[ij.x]);
    float4 b0 = __ldg(&g_xyz4[ij.y]);
    float4 a1 = __ldg(&g_xyz4[ij.z]);
    float4 b1 = __ldg(&g_xyz4[ij.w]);

    atomicAdd(out + ij.x, bond_e(a0, b0, len.x, par.x));
    atomicAdd(out + ij.z, bond_e(a1, b1, len.y, par.y));
}

// Tail for odd bond counts
__global__ void __launch_bounds__(128)
bond_energy_tail_kernel(const int2*  __restrict__ adj,
                        const float* __restrict__ blen,
                        const float* __restrict__ bpar,
                        float* __restrict__ out,
                        int start, int nbonds)
{
    int e = start + blockIdx.x * blockDim.x + threadIdx.x;
    if (e >= nbonds) return;
    int2 ij = __ldg(adj + e);
    float4 a = __ldg(&g_xyz4[ij.x]);
    float4 b = __ldg(&g_xyz4[ij.y]);
    atomicAdd(out + ij.x, bond_e(a, b, __ldg(blen + e), __ldg(bpar + e)));
}

extern "C" void kernel_launch(void* const* d_in, const int* in_sizes, int n_in,
                              void* d_out, int out_size)
{
    const float* xyz  = (const float*)d_in[0];  // [N,3]
    const int2*  adj  = (const int2*)d_in[1];   // [E,2] int32
    const float* blen = (const float*)d_in[2];  // [E,1]
    const float* bpar = (const float*)d_in[3];  // [E,1]
    float*       out  = (float*)d_out;          // [N,1]

    int nbonds = in_sizes[1] / 2;
    int natoms = out_size;
    int npairs = nbonds / 2;
    int tail   = npairs * 2;

    {
        int threads = 256;
        prep_kernel<<<(natoms + threads - 1) / threads, threads>>>(xyz, out, natoms);
    }
    if (npairs > 0) {
        int threads = 256;
        bond_energy_kernel<<<(npairs + threads - 1) / threads, threads>>>(
            (const int4*)adj, (const float2*)blen, (const float2*)bpar, out, npairs);
    }
    if (tail < nbonds) {
        int threads = 128;
        int n = nbonds - tail;
        bond_energy_tail_kernel<<<(n + threads - 1) / threads, threads>>>(
            adj, blen, bpar, out, tail, nbonds);
    }
}